// round 3
// baseline (speedup 1.0000x reference)
#include <cuda_runtime.h>
#include <cuda_bf16.h>
#include <cstdint>

// FlaxHouseholderRoPE: B=2, S=4096, H=32, D=128, R=2, fp32.
// Inputs: q (B,S,H,D), k (B,S,H,D), pos (S), reflectors (H,R,D)  [f32]
// Output: concat(q_out, k_out).
//
// Prologue:
//   g_tab[s][lane]  = (cos a_{2l}, sin a_{2l}, cos a_{2l+1}, sin a_{2l+1})  (2 MB)
//   g_wrefl[h][r][] = w_r = 2*v_r/(|v_r|^2+eps)                             (32 KB)
//   g_scal[h]       = (A0, A1, g, 0),  A_r = (|v_r|^2+eps)/2,  g = dot(w0,w1)
// Main: one warp per (s,h), processes q&k for BOTH b. Householder as
//   c0 = A0*dot(x,w0); c1 = A1*(dot(x,w1) - c0*g); x -= c0*w0 + c1*w1
// (identical to two sequential reflections). RoPE via table.

#define BB 2
#define SS 4096
#define HH 32
#define DD 128
#define SH (SS * HH)               // 131072
#define NVEC (BB * SH)             // 262144 vectors per tensor
#define TAB_BLOCKS 512

__device__ float4 g_tab[SS * 32];
__device__ float4 g_wrefl[HH * 2 * 32];
__device__ float4 g_scal[HH];

__device__ __forceinline__ float dot4(float4 a, float4 b) {
    return a.x * b.x + a.y * b.y + a.z * b.z + a.w * b.w;
}

__global__ __launch_bounds__(256)
void prologue_kernel(const float* __restrict__ pos,
                     const float* __restrict__ refl) {
    if (blockIdx.x < TAB_BLOCKS) {
        const int j = blockIdx.x * 256 + threadIdx.x;   // 0 .. 131071
        const int s = j >> 5;
        const int t = j & 31;
        const float p = pos[s];
        const float LOG2_BASE = 13.287712379549449f;    // log2(10000)
        const float f0 = exp2f(-(float)(4 * t)     * (1.0f / 128.0f) * LOG2_BASE);
        const float f1 = exp2f(-(float)(4 * t + 2) * (1.0f / 128.0f) * LOG2_BASE);
        float s0, c0, s1, c1;
        sincosf(p * f0, &s0, &c0);
        sincosf(p * f1, &s1, &c1);
        g_tab[j] = make_float4(c0, s0, c1, s1);
    } else {
        // one warp per head h: build w0, w1, and (A0, A1, g)
        const int wb   = blockIdx.x - TAB_BLOCKS;
        const int h    = wb * 8 + ((int)threadIdx.x >> 5);
        const int lane = threadIdx.x & 31;
        if (h < HH) {
            const float4 v0 = reinterpret_cast<const float4*>(refl)[(h * 2 + 0) * 32 + lane];
            const float4 v1 = reinterpret_cast<const float4*>(refl)[(h * 2 + 1) * 32 + lane];
            float sq0 = dot4(v0, v0), sq1 = dot4(v1, v1);
            #pragma unroll
            for (int o = 16; o; o >>= 1) {
                sq0 += __shfl_xor_sync(0xffffffffu, sq0, o);
                sq1 += __shfl_xor_sync(0xffffffffu, sq1, o);
            }
            const float SQ0 = sq0 + 1e-6f, SQ1 = sq1 + 1e-6f;
            const float r0 = 2.0f / SQ0,   r1 = 2.0f / SQ1;
            const float4 w0 = make_float4(v0.x * r0, v0.y * r0, v0.z * r0, v0.w * r0);
            const float4 w1 = make_float4(v1.x * r1, v1.y * r1, v1.z * r1, v1.w * r1);
            g_wrefl[(h * 2 + 0) * 32 + lane] = w0;
            g_wrefl[(h * 2 + 1) * 32 + lane] = w1;
            float g = dot4(w0, w1);
            #pragma unroll
            for (int o = 16; o; o >>= 1) g += __shfl_xor_sync(0xffffffffu, g, o);
            if (lane == 0)
                g_scal[h] = make_float4(SQ0 * 0.5f, SQ1 * 0.5f, g, 0.0f);
        }
    }
}

__global__ __launch_bounds__(256)
void hh_rope_kernel(const float* __restrict__ q,
                    const float* __restrict__ k,
                    float* __restrict__ out) {
    const int gw   = (blockIdx.x * blockDim.x + threadIdx.x) >> 5;  // (s,h): 0..SH-1
    const int lane = threadIdx.x & 31;
    const int h = gw & (HH - 1);
    const int s = gw >> 5;

    const float4* q4 = reinterpret_cast<const float4*>(q);
    const float4* k4 = reinterpret_cast<const float4*>(k);

    const size_t off0 = (size_t)gw * 32 + lane;            // b = 0
    const size_t off1 = (size_t)(SH + gw) * 32 + lane;     // b = 1

    // ---- front-batched streamed loads (4 independent LDG.128) ----
    float4 xq0 = __ldcs(q4 + off0);
    float4 xq1 = __ldcs(q4 + off1);
    float4 xk0 = __ldcs(k4 + off0);
    float4 xk1 = __ldcs(k4 + off1);

    // ---- shared operands (L1-resident) ----
    const float4 w0 = g_wrefl[(h * 2 + 0) * 32 + lane];
    const float4 w1 = g_wrefl[(h * 2 + 1) * 32 + lane];
    const float4 sc = g_scal[h];                 // (A0, A1, g, -)
    const float4 cs = g_tab[s * 32 + lane];      // (c0, s0, c1, s1)

    // ---- 8 dots, single butterfly phase ----
    float d0 = dot4(xq0, w0), d1 = dot4(xq0, w1);
    float d2 = dot4(xq1, w0), d3 = dot4(xq1, w1);
    float d4 = dot4(xk0, w0), d5 = dot4(xk0, w1);
    float d6 = dot4(xk1, w0), d7 = dot4(xk1, w1);
    #pragma unroll
    for (int o = 16; o; o >>= 1) {
        d0 += __shfl_xor_sync(0xffffffffu, d0, o);
        d1 += __shfl_xor_sync(0xffffffffu, d1, o);
        d2 += __shfl_xor_sync(0xffffffffu, d2, o);
        d3 += __shfl_xor_sync(0xffffffffu, d3, o);
        d4 += __shfl_xor_sync(0xffffffffu, d4, o);
        d5 += __shfl_xor_sync(0xffffffffu, d5, o);
        d6 += __shfl_xor_sync(0xffffffffu, d6, o);
        d7 += __shfl_xor_sync(0xffffffffu, d7, o);
    }

    // ---- apply both reflections + RoPE, per stream ----
    auto apply = [&](float4& x, float da, float db) {
        const float c0 = sc.x * da;
        const float c1 = sc.y * (db - c0 * sc.z);
        x.x -= c0 * w0.x + c1 * w1.x;
        x.y -= c0 * w0.y + c1 * w1.y;
        x.z -= c0 * w0.z + c1 * w1.z;
        x.w -= c0 * w0.w + c1 * w1.w;
        float4 o;
        o.x = x.x * cs.x - x.y * cs.y;
        o.y = x.x * cs.y + x.y * cs.x;
        o.z = x.z * cs.z - x.w * cs.w;
        o.w = x.z * cs.w + x.w * cs.z;
        x = o;
    };
    apply(xq0, d0, d1);
    apply(xq1, d2, d3);
    apply(xk0, d4, d5);
    apply(xk1, d6, d7);

    float4* out4 = reinterpret_cast<float4*>(out);
    __stcs(out4 + off0, xq0);                               // q, b=0
    __stcs(out4 + off1, xq1);                               // q, b=1
    __stcs(out4 + (size_t)NVEC * 32 + off0, xk0);           // k, b=0
    __stcs(out4 + (size_t)NVEC * 32 + off1, xk1);           // k, b=1
}

extern "C" void kernel_launch(void* const* d_in, const int* in_sizes, int n_in,
                              void* d_out, int out_size) {
    const float* q    = (const float*)d_in[0];
    const float* k    = (const float*)d_in[1];
    const float* pos  = (const float*)d_in[2];
    const float* refl = (const float*)d_in[3];
    float* out = (float*)d_out;

    prologue_kernel<<<TAB_BLOCKS + 4, 256>>>(pos, refl);
    // one warp per (s,h): 131072 warps, 8 per block
    hh_rope_kernel<<<SH / 8, 256>>>(q, k, out);
}

// round 4
// speedup vs baseline: 1.0537x; 1.0537x over previous
#include <cuda_runtime.h>
#include <cuda_bf16.h>
#include <cstdint>

// FlaxHouseholderRoPE: B=2, S=4096, H=32, D=128, R=2, fp32.
// Inputs: q (B,S,H,D), k (B,S,H,D), pos (S), reflectors (H,R,D)  [f32]
// Output: concat(q_out, k_out).
//
// Prologue:
//   g_tab[s][lane] = (cos a_{2l}, sin a_{2l}, cos a_{2l+1}, sin a_{2l+1})  (2 MB)
//   g_u[h][r][:]   = v * sqrt(2/(|v|^2+eps))   -- normalized reflector (32 KB)
// Main: one warp per (b,s,h), processes q AND k.
//   Reflection r:  x -= dot(x, u_r) * u_r     (== 2*dot(x,v)/(|v|^2+eps) * v)
//   RoPE via table. 5x LDG.128 + 2x STG.128 per warp, ~32 regs.

#define BB 2
#define SS 4096
#define HH 32
#define DD 128
#define NVEC (BB * SS * HH)        // 262144 vectors per tensor
#define TAB_BLOCKS 512

__device__ float4 g_tab[SS * 32];
__device__ float4 g_u[HH * 2 * 32];

__device__ __forceinline__ float dot4(float4 a, float4 b) {
    return a.x * b.x + a.y * b.y + a.z * b.z + a.w * b.w;
}

__global__ __launch_bounds__(256)
void prologue_kernel(const float* __restrict__ pos,
                     const float* __restrict__ refl) {
    if (blockIdx.x < TAB_BLOCKS) {
        const int j = blockIdx.x * 256 + threadIdx.x;   // 0 .. 131071
        const int s = j >> 5;
        const int t = j & 31;
        const float p = pos[s];
        const float LOG2_BASE = 13.287712379549449f;    // log2(10000)
        const float f0 = exp2f(-(float)(4 * t)     * (1.0f / 128.0f) * LOG2_BASE);
        const float f1 = exp2f(-(float)(4 * t + 2) * (1.0f / 128.0f) * LOG2_BASE);
        float s0, c0, s1, c1;
        sincosf(p * f0, &s0, &c0);
        sincosf(p * f1, &s1, &c1);
        g_tab[j] = make_float4(c0, s0, c1, s1);
    } else {
        // one warp per reflector row (h,r): 64 rows
        const int wb   = blockIdx.x - TAB_BLOCKS;
        const int row  = wb * 8 + ((int)threadIdx.x >> 5);
        const int lane = threadIdx.x & 31;
        if (row < HH * 2) {
            const float4 v = reinterpret_cast<const float4*>(refl)[row * 32 + lane];
            float sq = dot4(v, v);
            #pragma unroll
            for (int o = 16; o; o >>= 1) sq += __shfl_xor_sync(0xffffffffu, sq, o);
            const float sc = sqrtf(2.0f / (sq + 1e-6f));
            g_u[row * 32 + lane] = make_float4(v.x * sc, v.y * sc, v.z * sc, v.w * sc);
        }
    }
}

__global__ __launch_bounds__(256)
void hh_rope_kernel(const float* __restrict__ q,
                    const float* __restrict__ k,
                    float* __restrict__ out) {
    const int idx  = (blockIdx.x * blockDim.x + threadIdx.x) >> 5;  // (b*S+s)*H + h
    const int lane = threadIdx.x & 31;

    const int h = idx & (HH - 1);
    const int s = (idx >> 5) & (SS - 1);

    const size_t off = (size_t)idx * 32 + lane;

    // ---- streamed loads (coalesced LDG.128, evict-first) ----
    float4 xq = __ldcs(reinterpret_cast<const float4*>(q) + off);
    float4 xk = __ldcs(reinterpret_cast<const float4*>(k) + off);

    // ---- two sequential normalized-Householder reflections on q and k ----
    #pragma unroll
    for (int r = 0; r < 2; ++r) {
        const float4 u = g_u[(h * 2 + r) * 32 + lane];   // L1 hit
        float dq = dot4(xq, u);
        float dk = dot4(xk, u);
        #pragma unroll
        for (int o = 16; o; o >>= 1) {
            dq += __shfl_xor_sync(0xffffffffu, dq, o);
            dk += __shfl_xor_sync(0xffffffffu, dk, o);
        }
        xq.x -= dq * u.x;  xq.y -= dq * u.y;  xq.z -= dq * u.z;  xq.w -= dq * u.w;
        xk.x -= dk * u.x;  xk.y -= dk * u.y;  xk.z -= dk * u.z;  xk.w -= dk * u.w;
    }

    // ---- RoPE via table (same row across the block's 8 warps -> L1 broadcast) ----
    const float4 cs = g_tab[s * 32 + lane];   // (c0, s0, c1, s1)

    float4 oq, ok;
    oq.x = xq.x * cs.x - xq.y * cs.y;
    oq.y = xq.x * cs.y + xq.y * cs.x;
    oq.z = xq.z * cs.z - xq.w * cs.w;
    oq.w = xq.z * cs.w + xq.w * cs.z;
    ok.x = xk.x * cs.x - xk.y * cs.y;
    ok.y = xk.x * cs.y + xk.y * cs.x;
    ok.z = xk.z * cs.z - xk.w * cs.w;
    ok.w = xk.z * cs.w + xk.w * cs.z;

    float4* out4 = reinterpret_cast<float4*>(out);
    __stcs(out4 + off, oq);                              // q half
    __stcs(out4 + (size_t)NVEC * 32 + off, ok);          // k half
}

extern "C" void kernel_launch(void* const* d_in, const int* in_sizes, int n_in,
                              void* d_out, int out_size) {
    const float* q    = (const float*)d_in[0];
    const float* k    = (const float*)d_in[1];
    const float* pos  = (const float*)d_in[2];
    const float* refl = (const float*)d_in[3];
    float* out = (float*)d_out;

    prologue_kernel<<<TAB_BLOCKS + 8, 256>>>(pos, refl);
    // one warp per (b,s,h): 262144 warps, 8 per block
    hh_rope_kernel<<<NVEC / 8, 256>>>(q, k, out);
}